// round 1
// baseline (speedup 1.0000x reference)
#include <cuda_runtime.h>
#include <cuda_fp16.h>
#include <cstdint>
#include <cstddef>

#define QN 512
#define SN 64
#define BN 64
#define TN 256

// Scratch tables (device globals — no allocation allowed in kernel_launch).
// e16[s][i][j] = fp16( exp(A[i,s,j]) * Q - 1 ), row-major in j.  32 MB.
static __device__ __align__(16) __half2 g_e16[(size_t)SN * QN * QN / 2];
// rs[s*Q + i] = sum_j float(e16[s][i][j])  (row sums of the QUANTIZED table)
static __device__ float g_rs[SN * QN];

__device__ __forceinline__ __half2 u2h(unsigned u) { return *reinterpret_cast<__half2*>(&u); }
__device__ __forceinline__ unsigned h2u(__half2 h) { return *reinterpret_cast<unsigned*>(&h); }

// ---------------------------------------------------------------------------
// Prep: build fp16 residual table + exact row sums of the quantized values.
// One warp per (s,i) row. 4096 blocks x 256 threads.
// ---------------------------------------------------------------------------
__global__ void __launch_bounds__(256) fsa_prep(const float* __restrict__ A) {
    const float LN_Q = 6.2383246250395077847f;  // ln(512)
    int rowid = blockIdx.x * 8 + (threadIdx.x >> 5);
    int lane  = threadIdx.x & 31;
    int s = rowid >> 9;         // rowid / Q
    int i = rowid & (QN - 1);   // rowid % Q
    const float* arow = A + ((size_t)i * SN + s) * QN;
    __half2* erow = g_e16 + (size_t)rowid * (QN / 2);
    float rs = 0.f;
#pragma unroll
    for (int c = 0; c < 8; ++c) {
        int j2 = c * 32 + lane;              // half2 index within row (0..255)
        // exp(A)*Q - 1 = expm1(A + ln Q), computed at full fp32 precision
        float e0 = expm1f(arow[2 * j2]     + LN_Q);
        float e1 = expm1f(arow[2 * j2 + 1] + LN_Q);
        __half2 h = __floats2half2_rn(e0, e1);
        erow[j2] = h;
        float2 fb = __half22float2(h);       // sum the quantized values (consistency!)
        rs += fb.x + fb.y;
    }
#pragma unroll
    for (int o = 16; o > 0; o >>= 1) rs += __shfl_xor_sync(0xffffffffu, rs, o);
    if (lane == 0) g_rs[rowid] = rs;
}

// ---------------------------------------------------------------------------
// Main: one 2-CTA cluster per sequence. CTA rank owns rows [rank*256, +256).
// Per step:  alpha'_i = (1/Q) * ( S + m*RS_i(sym) + m*(1/USCALE)*sum_j e_ij*us_j )
// where us_j = (alpha_j/m - 1)*USCALE lives in smem as half2.
// ---------------------------------------------------------------------------
__global__ void __cluster_dims__(2, 1, 1) __launch_bounds__(512, 1)
fsa_main(const float* __restrict__ initw, const float* __restrict__ finalw,
         const int* __restrict__ xs, float* __restrict__ out)
{
    __shared__ __align__(16) float   s_alpha[QN];
    __shared__ __align__(16) __half2 s_us[QN / 2];
    __shared__ float s_wsum[16];
    __shared__ float s_scal[2];   // [0] = S = sum(alpha), [1] = m = S/Q
    __shared__ int   s_sym[TN];

    const float USCALE = 1024.0f, INV_USCALE = 1.0f / 1024.0f, INV_Q = 1.0f / (float)QN;

    unsigned rank;
    asm("mov.u32 %0, %%cluster_ctarank;" : "=r"(rank));
    int b    = blockIdx.x >> 1;
    int tid  = threadIdx.x;
    int wid  = tid >> 5;
    int lane = tid & 31;

    for (int t = tid; t < TN; t += 512) s_sym[t] = xs[b * TN + t];
    s_alpha[tid] = expf(initw[tid]);   // alpha_0 (computed redundantly in both CTAs)
    __syncthreads();

    // ---- compute S, m, us from s_alpha (uniform across both CTAs) ----
#define RECOMPUTE_STATS()                                                        \
    {                                                                            \
        float v = s_alpha[tid];                                                  \
        _Pragma("unroll")                                                        \
        for (int o = 16; o > 0; o >>= 1) v += __shfl_xor_sync(0xffffffffu, v, o);\
        if (lane == 0) s_wsum[wid] = v;                                          \
        __syncthreads();                                                         \
        if (wid == 0) {                                                          \
            float w = (lane < 16) ? s_wsum[lane] : 0.f;                          \
            _Pragma("unroll")                                                    \
            for (int o = 8; o > 0; o >>= 1) w += __shfl_xor_sync(0xffffffffu, w, o);\
            if (lane == 0) { s_scal[0] = w; s_scal[1] = w * INV_Q; }             \
        }                                                                        \
        __syncthreads();                                                         \
        float invm = 1.0f / s_scal[1];                                           \
        if (tid < QN / 2) {                                                      \
            float u0 = (s_alpha[2 * tid]     * invm - 1.0f) * USCALE;            \
            float u1 = (s_alpha[2 * tid + 1] * invm - 1.0f) * USCALE;            \
            s_us[tid] = __floats2half2_rn(u0, u1);                               \
        }                                                                        \
        __syncthreads();                                                         \
    }

    RECOMPUTE_STATS();

    const int i0 = (int)rank * 256 + wid * 16;   // this warp's first output row

    for (int t = 0; t < TN; ++t) {
        int sym = s_sym[t];
        const uint4* mrow = reinterpret_cast<const uint4*>(
            g_e16 + ((size_t)(sym * QN + i0)) * (QN / 2));  // 64 uint4 per row

        // u vector chunks for this lane: j in [8l,8l+8) and [256+8l, 256+8l+8)
        uint4 ua = *reinterpret_cast<const uint4*>(s_us + 4 * lane);
        uint4 ub = *reinterpret_cast<const uint4*>(s_us + 128 + 4 * lane);
        float Ssum = s_scal[0];
        float m    = s_scal[1];

        __half2 acc[16];
#pragma unroll
        for (int r = 0; r < 16; ++r) {
            const uint4* rp = mrow + (size_t)r * 64;
            uint4 va = rp[lane];        // 512B coalesced
            uint4 vb = rp[32 + lane];   // 512B coalesced
            __half2 a;
            a = __hmul2(u2h(va.x), u2h(ua.x));
            a = __hfma2(u2h(va.y), u2h(ua.y), a);
            a = __hfma2(u2h(va.z), u2h(ua.z), a);
            a = __hfma2(u2h(va.w), u2h(ua.w), a);
            a = __hfma2(u2h(vb.x), u2h(ub.x), a);
            a = __hfma2(u2h(vb.y), u2h(ub.y), a);
            a = __hfma2(u2h(vb.z), u2h(ub.z), a);
            a = __hfma2(u2h(vb.w), u2h(ub.w), a);
            acc[r] = a;
        }

        // butterfly-reduce all 16 rows (independent chains -> good ILP)
        float dotv = 0.f;
#pragma unroll
        for (int r = 0; r < 16; ++r) {
            __half2 v = acc[r];
#pragma unroll
            for (int o = 16; o > 0; o >>= 1) {
                unsigned uu = h2u(v);
                uu = __shfl_xor_sync(0xffffffffu, uu, o);
                v = __hadd2(v, u2h(uu));
            }
            if (lane == r) { float2 f = __half22float2(v); dotv = f.x + f.y; }
        }

        if (lane < 16) {
            int i = i0 + lane;
            float rs = g_rs[sym * QN + i];
            float an = INV_Q * (Ssum + m * (rs + dotv * INV_USCALE));
            s_alpha[i] = an;
            // mirror into the peer CTA's smem
            unsigned laddr = (unsigned)__cvta_generic_to_shared(&s_alpha[i]);
            unsigned raddr;
            asm("mapa.shared::cluster.u32 %0, %1, %2;" : "=r"(raddr) : "r"(laddr), "r"(rank ^ 1u));
            asm volatile("st.shared::cluster.f32 [%0], %1;" :: "r"(raddr), "f"(an));
        }

        // cluster barrier: orders the DSMEM stores, both CTAs now hold full alpha
        asm volatile("barrier.cluster.arrive.aligned;" ::: "memory");
        asm volatile("barrier.cluster.wait.aligned;"   ::: "memory");

        RECOMPUTE_STATS();
    }

    // termination: out[b] = log( sum_q alpha_T[q] * exp(final[q]) )
    if (rank == 0) {
        float v = s_alpha[tid] * expf(finalw[tid]);
#pragma unroll
        for (int o = 16; o > 0; o >>= 1) v += __shfl_xor_sync(0xffffffffu, v, o);
        if (lane == 0) s_wsum[wid] = v;
        __syncthreads();
        if (tid == 0) {
            float w = 0.f;
#pragma unroll
            for (int k = 0; k < 16; ++k) w += s_wsum[k];
            out[b] = logf(w);
        }
    }
}

// ---------------------------------------------------------------------------
// inputs (metadata order): A (Q*S*Q f32), init (Q f32), final (Q f32), xs (B*T i32)
// output: (B,) f32
// ---------------------------------------------------------------------------
extern "C" void kernel_launch(void* const* d_in, const int* in_sizes, int n_in,
                              void* d_out, int out_size) {
    const float* A      = (const float*)d_in[0];
    const float* initw  = (const float*)d_in[1];
    const float* finalw = (const float*)d_in[2];
    const int*   xs     = (const int*)d_in[3];
    float*       out    = (float*)d_out;

    fsa_prep<<<SN * QN / 8, 256>>>(A);
    fsa_main<<<2 * BN, 512>>>(initw, finalw, xs, out);
}